// round 15
// baseline (speedup 1.0000x reference)
#include <cuda_runtime.h>
#include <cstdint>

#define BATCH 32
#define HW    16384          // 128*128
#define NPIX  (BATCH * HW)   // 524288
#define NMIXK 10
#define TPB   256
#define NBLK  (NPIX / TPB)   // 2048

__device__ double       g_part[NBLK];
__device__ unsigned int g_count = 0;

// ---- cp.async helpers (LDGSTS) ----
__device__ __forceinline__ void cp16(void* smem_dst, const void* gsrc) {
    uint32_t d = (uint32_t)__cvta_generic_to_shared(smem_dst);
    asm volatile("cp.async.cg.shared.global [%0], [%1], 16;" :: "r"(d), "l"(gsrc));
}
__device__ __forceinline__ void cp_commit() {
    asm volatile("cp.async.commit_group;");
}
template <int N>
__device__ __forceinline__ void cp_wait() {
    asm volatile("cp.async.wait_group %0;" :: "n"(N));
}

// hardware tanh: 1 MUFU op, abs err ~5e-4
__device__ __forceinline__ float tanh_hw(float v) {
    float r;
    asm("tanh.approx.f32 %0, %1;" : "=f"(r) : "f"(v));
    return r;
}

// per-(channel, mixture) log-prob: 3 MUFU (EX2, EX2, LG2). Body frozen (R13).
__device__ __forceinline__ float chlp(float x, float mu, float lsr) {
    float ls  = fmaxf(lsr, -7.0f);
    float inv = __expf(-ls);                             // MUFU 1
    float mid = inv * (x - mu);
    float d   = inv * (1.0f / 255.0f);                   // half-width > 0
    float am  = fabsf(mid);
    float g   = __expf(-am);                             // MUFU 2

    float d2 = d * d;
    float ch     = fmaf(d2, fmaf(d2, 4.1666667e-2f, 0.5f), 1.0f);
    float log_sc = d2 * fmaf(d2, -5.5555556e-3f, 0.16666667f);  // log(sinh d / d)

    if (d > 1.0f) {                                      // ultra-rare exact path
        float ed = __expf(d), edi = __expf(-d);
        ch     = 0.5f * (ed + edi);
        log_sc = __logf(0.5f * (ed - edi) * __fdividef(1.0f, d));
    }

    float denom = fmaf(2.0f * ch, g, fmaf(g, g, 1.0f));
    float inner = -ls - 4.8481164f - am - __logf(denom) + log_sc;  // MUFU 3

    // rare edge cases (|x| > 0.999): predicated, ~0.05% of pixels
    if (x < -0.999f) {
        float pz = mid + d;
        inner = fminf(pz, 0.0f) - __logf(1.0f + __expf(-fabsf(pz)));
    } else if (x > 0.999f) {
        float q = mid - d;
        inner = -fmaxf(q, 0.0f) - __logf(1.0f + __expf(-fabsf(q)));
    }
    return inner;
}

// stage m = the 10 param rows of mixture m: rows m+10k, k=0..9, 256 floats each.
// 640 float4 per stage; thread t copies indices t, t+256, t+512.
__device__ __forceinline__ void issue_stage(float* dst /*[10*256]*/,
                                            const float* gbase, int m, int t) {
    #pragma unroll
    for (int i = 0; i < 3; i++) {
        int idx = t + i * 256;
        if (idx < 640) {
            int k = idx >> 6;          // row group 0..9
            int e = idx & 63;          // float4 within row
            const float* src = gbase + (size_t)(k * 10 + m) * HW + 4 * e;
            cp16(dst + k * 256 + 4 * e, src);
        }
    }
    cp_commit();
}

__global__ void __launch_bounds__(TPB, 8) pixlp_kernel(
    const float* __restrict__ samples, const float* __restrict__ params,
    float* __restrict__ out)
{
    __shared__ float buf[2][NMIXK * 256];   // 20.5 KB double-buffered stage
    __shared__ float red[TPB];

    int t  = threadIdx.x;
    int p  = blockIdx.x * TPB + t;
    int b  = p >> 14;
    int hw = p & (HW - 1);
    int hw0 = (blockIdx.x * TPB) & (HW - 1);            // block-aligned, 1KB aligned
    const float* sp    = samples + (size_t)b * 3   * HW + hw;
    const float* gbase = params  + (size_t)b * 100 * HW + hw0;

    // pipeline prologue: stages 0 and 1 in flight
    issue_stage(buf[0], gbase, 0, t);
    issue_stage(buf[1], gbase, 1, t);

    float x0 = fmaf(2.0f, __ldg(sp),          -1.0f);
    float x1 = fmaf(2.0f, __ldg(sp + HW),     -1.0f);
    float x2 = fmaf(2.0f, __ldg(sp + 2 * HW), -1.0f);

    float se = 0.0f;        // sum exp(logits) — |logits| small, overflow-safe
    float lp[NMIXK];        // independent per-mixture results -> full ILP

    #pragma unroll
    for (int m = 0; m < NMIXK; m++) {
        if (m < NMIXK - 1) cp_wait<1>(); else cp_wait<0>();   // stage m landed
        __syncthreads();

        const float* s = buf[m & 1];
        float lg  = s[0 * 256 + t];
        float mu1 = s[1 * 256 + t];
        float ls1 = s[2 * 256 + t];
        float c0r = s[3 * 256 + t];
        float mu2 = s[4 * 256 + t];
        float ls2 = s[5 * 256 + t];
        float c1r = s[6 * 256 + t];
        float mu3 = s[7 * 256 + t];
        float ls3 = s[8 * 256 + t];
        float c2r = s[9 * 256 + t];

        se += __expf(lg);

        float c0 = tanh_hw(c0r);
        float c1 = tanh_hw(c1r);
        float c2 = tanh_hw(c2r);
        float m2 = fmaf(c0, x0, mu2);
        float m3 = fmaf(c2, x1, fmaf(c1, x0, mu3));

        lp[m] = lg + chlp(x0, mu1, ls1)
                   + chlp(x1, m2,  ls2)
                   + chlp(x2, m3,  ls3);

        if (m + 2 < NMIXK) {
            __syncthreads();                           // all done reading buf[m&1]
            issue_stage(buf[m & 1], gbase, m + 2, t);  // refill with stage m+2
        }
    }

    float mx2 = lp[0];
    #pragma unroll
    for (int i = 1; i < NMIXK; i++) mx2 = fmaxf(mx2, lp[i]);
    float s2 = 0.0f;
    #pragma unroll
    for (int i = 0; i < NMIXK; i++) s2 += __expf(lp[i] - mx2);

    float val = mx2 + __logf(s2) - __logf(se);

    // block reduction (fp32 within block)
    red[t] = val;
    __syncthreads();
    #pragma unroll
    for (int off = TPB / 2; off > 32; off >>= 1) {
        if (t < off) red[t] += red[t + off];
        __syncthreads();
    }
    if (t < 32) {
        float w = red[t] + red[t + 32];
        #pragma unroll
        for (int off = 16; off > 0; off >>= 1)
            w += __shfl_down_sync(0xFFFFFFFFu, w, off);
        if (t == 0) red[0] = w;
    }
    __syncthreads();

    // block partial (double), last block finishes — no helper kernels
    __shared__ bool amLast;
    if (t == 0) {
        g_part[blockIdx.x] = (double)red[0];
        __threadfence();
        unsigned int done = atomicAdd(&g_count, 1u);
        amLast = (done == NBLK - 1);
    }
    __syncthreads();

    if (amLast) {
        __shared__ double redd[TPB];
        double sd = 0.0;
        for (int i = t; i < NBLK; i += TPB) sd += g_part[i];
        redd[t] = sd;
        __syncthreads();
        #pragma unroll
        for (int off = TPB / 2; off > 0; off >>= 1) {
            if (t < off) redd[t] += redd[t + off];
            __syncthreads();
        }
        if (t == 0) {
            out[0] = (float)redd[0];
            g_count = 0;                      // reset for next graph replay
        }
    }
}

extern "C" void kernel_launch(void* const* d_in, const int* in_sizes, int n_in,
                              void* d_out, int out_size)
{
    const float* samples;
    const float* params;
    if (in_sizes[0] == BATCH * 3 * HW) {
        samples = (const float*)d_in[0];
        params  = (const float*)d_in[1];
    } else {
        samples = (const float*)d_in[1];
        params  = (const float*)d_in[0];
    }
    pixlp_kernel<<<NBLK, TPB>>>(samples, params, (float*)d_out);
}

// round 16
// speedup vs baseline: 1.4012x; 1.4012x over previous
#include <cuda_runtime.h>

#define BATCH 32
#define HW    16384          // 128*128
#define NPIX  (BATCH * HW)   // 524288
#define NMIXK 10
#define TPB   256
#define NBLK  (NPIX / TPB)   // 2048

__device__ double       g_part[NBLK];
__device__ unsigned int g_count = 0;

// hardware tanh: 1 MUFU op, abs err ~5e-4
__device__ __forceinline__ float tanh_hw(float v) {
    float r;
    asm("tanh.approx.f32 %0, %1;" : "=f"(r) : "f"(v));
    return r;
}

// non-coherent load with 256B L2 prefetch: same issue slot, 2x in-flight DRAM
// bytes per request (second 128B = the adjacent CTA's segment of the row).
__device__ __forceinline__ float ldg_pf(const float* p) {
    float v;
    asm("ld.global.nc.L2::256B.f32 %0, [%1];" : "=f"(v) : "l"(p));
    return v;
}

// per-(channel, mixture) log-prob: 3 MUFU (EX2, EX2, LG2). Body frozen (R13).
__device__ __forceinline__ float chlp(float x, float mu, float lsr) {
    float ls  = fmaxf(lsr, -7.0f);
    float inv = __expf(-ls);                             // MUFU 1
    float mid = inv * (x - mu);
    float d   = inv * (1.0f / 255.0f);                   // half-width > 0
    float am  = fabsf(mid);
    float g   = __expf(-am);                             // MUFU 2

    float d2 = d * d;
    float ch     = fmaf(d2, fmaf(d2, 4.1666667e-2f, 0.5f), 1.0f);
    float log_sc = d2 * fmaf(d2, -5.5555556e-3f, 0.16666667f);  // log(sinh d / d)

    if (d > 1.0f) {                                      // ultra-rare exact path
        float ed = __expf(d), edi = __expf(-d);
        ch     = 0.5f * (ed + edi);
        log_sc = __logf(0.5f * (ed - edi) * __fdividef(1.0f, d));
    }

    float denom = fmaf(2.0f * ch, g, fmaf(g, g, 1.0f));
    float inner = -ls - 4.8481164f - am - __logf(denom) + log_sc;  // MUFU 3

    // rare edge cases (|x| > 0.999): predicated, ~0.05% of pixels
    if (x < -0.999f) {
        float pz = mid + d;
        inner = fminf(pz, 0.0f) - __logf(1.0f + __expf(-fabsf(pz)));
    } else if (x > 0.999f) {
        float q = mid - d;
        inner = -fmaxf(q, 0.0f) - __logf(1.0f + __expf(-fabsf(q)));
    }
    return inner;
}

__global__ void __launch_bounds__(TPB, 8) pixlp_kernel(
    const float* __restrict__ samples, const float* __restrict__ params,
    float* __restrict__ out)
{
    int p  = blockIdx.x * TPB + threadIdx.x;
    int b  = p >> 14;
    int hw = p & (HW - 1);
    const float* sp = samples + (size_t)b * 3   * HW + hw;
    const float* pp = params  + (size_t)b * 100 * HW + hw;

    float x0 = fmaf(2.0f, __ldg(sp),          -1.0f);
    float x1 = fmaf(2.0f, __ldg(sp + HW),     -1.0f);
    float x2 = fmaf(2.0f, __ldg(sp + 2 * HW), -1.0f);

    float se = 0.0f;        // sum exp(logits) — |logits| small, overflow-safe
    float lp[NMIXK];        // independent per-mixture results -> full ILP

    #pragma unroll
    for (int m = 0; m < NMIXK; m++) {
        float lg  = ldg_pf(pp + (     m) * HW);
        float mu1 = ldg_pf(pp + (10 + m) * HW);
        float ls1 = ldg_pf(pp + (20 + m) * HW);
        float c0r = ldg_pf(pp + (30 + m) * HW);
        float mu2 = ldg_pf(pp + (40 + m) * HW);
        float ls2 = ldg_pf(pp + (50 + m) * HW);
        float c1r = ldg_pf(pp + (60 + m) * HW);
        float mu3 = ldg_pf(pp + (70 + m) * HW);
        float ls3 = ldg_pf(pp + (80 + m) * HW);
        float c2r = ldg_pf(pp + (90 + m) * HW);

        se += __expf(lg);

        float c0 = tanh_hw(c0r);
        float c1 = tanh_hw(c1r);
        float c2 = tanh_hw(c2r);
        float m2 = fmaf(c0, x0, mu2);
        float m3 = fmaf(c2, x1, fmaf(c1, x0, mu3));

        lp[m] = lg + chlp(x0, mu1, ls1)
                   + chlp(x1, m2,  ls2)
                   + chlp(x2, m3,  ls3);
    }

    float mx2 = lp[0];
    #pragma unroll
    for (int i = 1; i < NMIXK; i++) mx2 = fmaxf(mx2, lp[i]);
    float s2 = 0.0f;
    #pragma unroll
    for (int i = 0; i < NMIXK; i++) s2 += __expf(lp[i] - mx2);

    float val = mx2 + __logf(s2) - __logf(se);

    // block reduction (fp32 within block)
    __shared__ float red[TPB];
    int t = threadIdx.x;
    red[t] = val;
    __syncthreads();
    #pragma unroll
    for (int off = TPB / 2; off > 32; off >>= 1) {
        if (t < off) red[t] += red[t + off];
        __syncthreads();
    }
    if (t < 32) {
        float w = red[t] + red[t + 32];
        #pragma unroll
        for (int off = 16; off > 0; off >>= 1)
            w += __shfl_down_sync(0xFFFFFFFFu, w, off);
        if (t == 0) red[0] = w;
    }
    __syncthreads();

    // block partial (double), last block finishes — no helper kernels
    __shared__ bool amLast;
    if (t == 0) {
        g_part[blockIdx.x] = (double)red[0];
        __threadfence();
        unsigned int done = atomicAdd(&g_count, 1u);
        amLast = (done == NBLK - 1);
    }
    __syncthreads();

    if (amLast) {
        __shared__ double redd[TPB];
        double sd = 0.0;
        for (int i = t; i < NBLK; i += TPB) sd += g_part[i];
        redd[t] = sd;
        __syncthreads();
        #pragma unroll
        for (int off = TPB / 2; off > 0; off >>= 1) {
            if (t < off) redd[t] += redd[t + off];
            __syncthreads();
        }
        if (t == 0) {
            out[0] = (float)redd[0];
            g_count = 0;                      // reset for next graph replay
        }
    }
}

extern "C" void kernel_launch(void* const* d_in, const int* in_sizes, int n_in,
                              void* d_out, int out_size)
{
    const float* samples;
    const float* params;
    if (in_sizes[0] == BATCH * 3 * HW) {
        samples = (const float*)d_in[0];
        params  = (const float*)d_in[1];
    } else {
        samples = (const float*)d_in[1];
        params  = (const float*)d_in[0];
    }
    pixlp_kernel<<<NBLK, TPB>>>(samples, params, (float*)d_out);
}